// round 11
// baseline (speedup 1.0000x reference)
#include <cuda_runtime.h>
#include <cuda_fp16.h>

#define NN 1000
#define DD 128
#define HR 500            // rows per CTA (cluster of 2 per batch)
#define RW 72             // tile row stride in words (288B, conflict-free)
#define NEGV (-1e9f)
typedef unsigned long long u64;
typedef unsigned int u32;

// ---- smem word offsets ----
#define O_TILE  0         // 500*72 = 36000 (fp16 tile, half2 words)
#define O_AT    36000     // 500*8  attn [n][8]
#define O_CP    40000     // 500*9  compat scratch / later s_lg
#define O_PART  44500     // 8192   partial reductions
#define O_QT    52692     // 1024   qt[d][8]
#define O_MEAN  53716
#define O_Q     53844
#define O_EF    53972
#define O_EL    54100
#define O_HEADS 54228
#define O_GL    54356
#define O_GT    54484
#define O_EBAR  54612     // 1024
#define O_RED   55636     // 64
#define O_XM    55700     // 128  exchange: mean partial
#define O_XS    55828     // 16   exchange: softmax max8+sum8
#define O_XE    55844     // 1024 exchange: ebar partial
#define O_XL    56868     // 4    exchange: lmax, lsum
#define SM_WORDS 56872    // 227488 bytes

static __device__ __forceinline__ u64 pack2(float a, float b) {
    u64 r; asm("mov.b64 %0, {%1, %2};" : "=l"(r) : "f"(a), "f"(b)); return r;
}
static __device__ __forceinline__ u64 packdup(float a) { return pack2(a, a); }
static __device__ __forceinline__ u64 fma2(u64 a, u64 b, u64 c) {
    u64 d; asm("fma.rn.f32x2 %0, %1, %2, %3;" : "=l"(d) : "l"(a), "l"(b), "l"(c)); return d;
}
static __device__ __forceinline__ float2 unpack2(u64 v) {
    float lo, hi; asm("mov.b64 {%0, %1}, %2;" : "=f"(lo), "=f"(hi) : "l"(v));
    return make_float2(lo, hi);
}
static __device__ __forceinline__ float tanh_fast(float x) {
    float y; asm("tanh.approx.f32 %0, %1;" : "=f"(y) : "f"(x)); return y;
}
static __device__ __forceinline__ float2 h2f(u32 w) {
    return __half22float2(*(__half2*)&w);
}
static __device__ __forceinline__ u32 f2h2(float a, float b) {
    __half2 h = __floats2half2_rn(a, b); return *(u32*)&h;
}
static __device__ __forceinline__ u32 ctarank() {
    u32 r; asm("mov.u32 %0, %%cluster_ctarank;" : "=r"(r)); return r;
}
static __device__ __forceinline__ float dsmem_ld(const float* p, u32 peer) {
    u32 la = (u32)__cvta_generic_to_shared(p), ra; float v;
    asm volatile("mapa.shared::cluster.u32 %0, %1, %2;" : "=r"(ra) : "r"(la), "r"(peer));
    asm volatile("ld.shared::cluster.f32 %0, [%1];" : "=f"(v) : "r"(ra));
    return v;
}
#define CLUSTER_SYNC() do { \
    asm volatile("barrier.cluster.arrive.aligned;" ::: "memory"); \
    asm volatile("barrier.cluster.wait.aligned;" ::: "memory"); } while (0)

extern "C" __global__ void __launch_bounds__(512, 1) __cluster_dims__(2, 1, 1)
attn_v8(const float* __restrict__ emb, const float* __restrict__ Wn,
        const float* __restrict__ Wf, const float* __restrict__ Ws,
        const float* __restrict__ Wo, const int* __restrict__ fidx,
        const int* __restrict__ lidx, const int* __restrict__ mask,
        float* __restrict__ out)
{
    extern __shared__ float sm[];
    const int t = threadIdx.x;
    const int lane = t & 31, warp = t >> 5;
    const int b = blockIdx.x >> 1;
    const u32 rank = ctarank();
    const u32 peer = rank ^ 1;
    const int rowbase = (int)rank * HR;
    const int* mkB = mask + (size_t)b * NN + rowbase;

    // ---- Phase 0: load own 500 rows fp32 -> fp16 tile + mean partials ----
    {
        int c = t & 31, g2 = t >> 5;
        const float4* E4 = (const float4*)(emb + ((size_t)b * NN + rowbase) * DD) + c;
        float4 acc = make_float4(0.f, 0.f, 0.f, 0.f);
        #pragma unroll 4
        for (int k = 0; k < 32; k++) {
            int r = g2 + (k << 4);
            if (r < HR) {
                float4 v = E4[(size_t)r * 32];
                acc.x += v.x; acc.y += v.y; acc.z += v.z; acc.w += v.w;
                uint2 h; h.x = f2h2(v.x, v.y); h.y = f2h2(v.z, v.w);
                *(uint2*)(sm + O_TILE + r * RW + c * 2) = h;
            }
        }
        *(float4*)(sm + O_PART + g2 * 128 + c * 4) = acc;
    }
    if (t < 128)      sm[O_EF + t] = emb[((size_t)b * NN + fidx[b]) * DD + t];
    else if (t < 256) sm[O_EL + t - 128] = emb[((size_t)b * NN + lidx[b]) * DD + (t - 128)];
    __syncthreads();
    if (t < 128) {
        float s = 0.f;
        #pragma unroll
        for (int g = 0; g < 16; g++) s += sm[O_PART + g * 128 + t];
        sm[O_XM + t] = s;
    }
    CLUSTER_SYNC();   // #1: exchange mean partials
    if (t < 128)
        sm[O_MEAN + t] = (sm[O_XM + t] + dsmem_ld(sm + O_XM + t, peer)) * (1.0f / NN);
    __syncthreads();

    // ---- q = mean@Wf + [ef;el]@Ws ----
    if (t < 128) {
        float acc = 0.f;
        #pragma unroll 4
        for (int i = 0; i < DD; i++) acc += sm[O_MEAN + i] * Wf[i * DD + t];
        #pragma unroll 4
        for (int i = 0; i < DD; i++) acc += sm[O_EF + i] * Ws[i * DD + t];
        #pragma unroll 4
        for (int i = 0; i < DD; i++) acc += sm[O_EL + i] * Ws[(DD + i) * DD + t];
        sm[O_Q + t] = acc;
    }
    __syncthreads();
    // ---- qt[d][8] ----
    if (t < 256) {
        int d = t >> 1, h0 = (t & 1) * 4;
        #pragma unroll
        for (int h = h0; h < h0 + 4; h++) {
            const float* w = Wn + d * 384 + h * 16;
            const float* qq = sm + O_Q + h * 16;
            float acc = 0.f;
            #pragma unroll
            for (int k = 0; k < 16; k++) acc += w[k] * qq[k];
            sm[O_QT + d * 8 + h] = acc * 0.25f;
        }
    }
    __syncthreads();

    // ---- Phase 1: compat (2 thr/row x 4 heads), all from smem ----
    {
        const int r_slot = t >> 1, q4 = t & 1;
        const ulonglong2* qtb = (const ulonglong2*)(sm + O_QT) + q4;
        for (int rd = 0; rd < 2; rd++) {
            int r = r_slot + rd * 256;
            if (r < HR) {
                const uint4* tp = (const uint4*)(sm + O_TILE + r * RW);
                u64 a01 = 0, a23 = 0;
                #pragma unroll
                for (int j = 0; j < 16; j++) {
                    uint4 e = tp[j];
                    const ulonglong2* qd = qtb + 16 * j;
                    float2 f; ulonglong2 qa;
                    f = h2f(e.x);
                    qa = qd[0];  a01 = fma2(packdup(f.x), qa.x, a01); a23 = fma2(packdup(f.x), qa.y, a23);
                    qa = qd[2];  a01 = fma2(packdup(f.y), qa.x, a01); a23 = fma2(packdup(f.y), qa.y, a23);
                    f = h2f(e.y);
                    qa = qd[4];  a01 = fma2(packdup(f.x), qa.x, a01); a23 = fma2(packdup(f.x), qa.y, a23);
                    qa = qd[6];  a01 = fma2(packdup(f.y), qa.x, a01); a23 = fma2(packdup(f.y), qa.y, a23);
                    f = h2f(e.z);
                    qa = qd[8];  a01 = fma2(packdup(f.x), qa.x, a01); a23 = fma2(packdup(f.x), qa.y, a23);
                    qa = qd[10]; a01 = fma2(packdup(f.y), qa.x, a01); a23 = fma2(packdup(f.y), qa.y, a23);
                    f = h2f(e.w);
                    qa = qd[12]; a01 = fma2(packdup(f.x), qa.x, a01); a23 = fma2(packdup(f.x), qa.y, a23);
                    qa = qd[14]; a01 = fma2(packdup(f.y), qa.x, a01); a23 = fma2(packdup(f.y), qa.y, a23);
                }
                int mk = mkB[r];
                float2 p01 = unpack2(a01), p23 = unpack2(a23);
                float* cp = sm + O_CP + r * 9 + q4 * 4;
                cp[0] = mk ? NEGV : p01.x;
                cp[1] = mk ? NEGV : p01.y;
                cp[2] = mk ? NEGV : p23.x;
                cp[3] = mk ? NEGV : p23.y;
            }
        }
    }
    __syncthreads();

    // ---- Phase 1b: per-head softmax stats (own half), exchange, normalize ----
    {
        int h = warp >> 1, seg = warp & 1;
        float mx = -1e30f;
        for (int n = seg * 32 + lane; n < HR; n += 64) mx = fmaxf(mx, sm[O_CP + n * 9 + h]);
        #pragma unroll
        for (int o = 16; o > 0; o >>= 1) mx = fmaxf(mx, __shfl_xor_sync(~0u, mx, o));
        if (lane == 0) sm[O_RED + warp] = mx;
        __syncthreads();
        float hm = fmaxf(sm[O_RED + 2 * h], sm[O_RED + 2 * h + 1]);
        float sme = 0.f;
        for (int n = seg * 32 + lane; n < HR; n += 64) sme += __expf(sm[O_CP + n * 9 + h] - hm);
        #pragma unroll
        for (int o = 16; o > 0; o >>= 1) sme += __shfl_xor_sync(~0u, sme, o);
        if (lane == 0) sm[O_RED + 16 + warp] = sme;
        __syncthreads();
        if (t < 8) {
            sm[O_XS + t]     = fmaxf(sm[O_RED + 2 * t], sm[O_RED + 2 * t + 1]);
            sm[O_XS + 8 + t] = sm[O_RED + 16 + 2 * t] + sm[O_RED + 16 + 2 * t + 1];
        }
    }
    CLUSTER_SYNC();   // #2: softmax stats
    if (t < 8) {
        float om = sm[O_XS + t], os = sm[O_XS + 8 + t];
        float pm = dsmem_ld(sm + O_XS + t, peer);
        float ps = dsmem_ld(sm + O_XS + 8 + t, peer);
        float M = fmaxf(om, pm);
        float S = os * __expf(om - M) + ps * __expf(pm - M);
        sm[O_RED + 32 + t] = M;
        sm[O_RED + 40 + t] = 1.0f / S;
    }
    __syncthreads();
    for (int i = t; i < HR * 8; i += 512) {
        int n = i >> 3, hh = i & 7;
        sm[O_AT + i] = __expf(sm[O_CP + n * 9 + hh] - sm[O_RED + 32 + hh]) * sm[O_RED + 40 + hh];
    }
    __syncthreads();

    // ---- Phase 2: ebar partials over own rows (dim-split, attn broadcast) ----
    {
        int p = t & 63, g = t >> 6;
        u64 a0 = 0, a1 = 0, a2 = 0, a3 = 0, a4 = 0, a5 = 0, a6 = 0, a7 = 0;
        for (int r = g; r < HR; r += 8) {
            u32 w = *(const u32*)(sm + O_TILE + r * RW + p);
            float2 f = h2f(w);
            const u64* at = (const u64*)(sm + O_AT + r * 8);
            u64 t0 = at[0], t1 = at[1], t2 = at[2], t3 = at[3];
            u64 d0 = packdup(f.x), d1 = packdup(f.y);
            a0 = fma2(d0, t0, a0); a1 = fma2(d0, t1, a1);
            a2 = fma2(d0, t2, a2); a3 = fma2(d0, t3, a3);
            a4 = fma2(d1, t0, a4); a5 = fma2(d1, t1, a5);
            a6 = fma2(d1, t2, a6); a7 = fma2(d1, t3, a7);
        }
        float* pp = sm + O_PART + g * 1024;
        float2 f;
        f = unpack2(a0); pp[0 * 128 + 2 * p] = f.x; pp[1 * 128 + 2 * p] = f.y;
        f = unpack2(a1); pp[2 * 128 + 2 * p] = f.x; pp[3 * 128 + 2 * p] = f.y;
        f = unpack2(a2); pp[4 * 128 + 2 * p] = f.x; pp[5 * 128 + 2 * p] = f.y;
        f = unpack2(a3); pp[6 * 128 + 2 * p] = f.x; pp[7 * 128 + 2 * p] = f.y;
        f = unpack2(a4); pp[0 * 128 + 2 * p + 1] = f.x; pp[1 * 128 + 2 * p + 1] = f.y;
        f = unpack2(a5); pp[2 * 128 + 2 * p + 1] = f.x; pp[3 * 128 + 2 * p + 1] = f.y;
        f = unpack2(a6); pp[4 * 128 + 2 * p + 1] = f.x; pp[5 * 128 + 2 * p + 1] = f.y;
        f = unpack2(a7); pp[6 * 128 + 2 * p + 1] = f.x; pp[7 * 128 + 2 * p + 1] = f.y;
    }
    __syncthreads();
    for (int i = t; i < 1024; i += 512) {
        float s = 0.f;
        #pragma unroll
        for (int g = 0; g < 8; g++) s += sm[O_PART + g * 1024 + i];
        sm[O_XE + i] = s;
    }
    CLUSTER_SYNC();   // #3: ebar partials
    for (int i = t; i < 1024; i += 512)
        sm[O_EBAR + i] = sm[O_XE + i] + dsmem_ld(sm + O_XE + i, peer);
    __syncthreads();

    // ---- heads -> glimpse -> gtilde (redundant in both CTAs) ----
    if (t < 128) {
        int h = t >> 4;
        const float* eb = sm + O_EBAR + h * 128;
        float acc = 0.f;
        #pragma unroll 4
        for (int d = 0; d < DD; d++) acc += eb[d] * Wn[d * 384 + 128 + t];
        sm[O_HEADS + t] = acc;
    }
    __syncthreads();
    if (t < 128) {
        float acc = 0.f;
        #pragma unroll 4
        for (int i = 0; i < DD; i++) acc += sm[O_HEADS + i] * Wo[i * DD + t];
        sm[O_GL + t] = acc;
    }
    __syncthreads();
    if (t < 128) {
        const float* w = Wn + t * 384 + 256;
        float acc = 0.f;
        #pragma unroll 4
        for (int j = 0; j < DD; j++) acc += w[j] * sm[O_GL + j];
        sm[O_GT + t] = acc * 0.08838834764831845f;
    }
    __syncthreads();

    // ---- Phase 3: logits own rows (2 thr/row, interleaved chunks) ----
    float* s_lg = sm + O_CP;   // reuse (500 floats)
    float lmax = -1e30f;
    {
        const int r_slot = t >> 1, p = t & 1;
        #pragma unroll
        for (int rd = 0; rd < 2; rd++) {
            int r0 = r_slot + rd * 256;
            int r = r0 < HR ? r0 : (HR - 1);
            const uint4* tp = (const uint4*)(sm + O_TILE + r * RW);
            u64 acc = 0;
            #pragma unroll
            for (int j = 0; j < 8; j++) {
                int k = 2 * j + p;
                uint4 e = tp[k];
                const u64* gp = (const u64*)(sm + O_GT) + 4 * k;
                float2 f;
                f = h2f(e.x); acc = fma2(pack2(f.x, f.y), gp[0], acc);
                f = h2f(e.y); acc = fma2(pack2(f.x, f.y), gp[1], acc);
                f = h2f(e.z); acc = fma2(pack2(f.x, f.y), gp[2], acc);
                f = h2f(e.w); acc = fma2(pack2(f.x, f.y), gp[3], acc);
            }
            float2 v = unpack2(acc);
            float s = v.x + v.y;
            s += __shfl_xor_sync(~0u, s, 1);
            if (p == 0 && r0 < HR) {
                float vv = tanh_fast(s) * 10.0f;
                if (mkB[r0] != 0) vv = NEGV;
                s_lg[r0] = vv;
                lmax = fmaxf(lmax, vv);
            }
        }
    }
    __syncthreads();
    // ---- own-half logsumexp, exchange, write ----
    #pragma unroll
    for (int o = 16; o > 0; o >>= 1) lmax = fmaxf(lmax, __shfl_xor_sync(~0u, lmax, o));
    if (lane == 0) sm[O_RED + warp] = lmax;
    __syncthreads();
    float bown = sm[O_RED + 0];
    #pragma unroll
    for (int w = 1; w < 16; w++) bown = fmaxf(bown, sm[O_RED + w]);
    float ls = 0.f;
    for (int n = t; n < HR; n += 512) ls += __expf(s_lg[n] - bown);
    #pragma unroll
    for (int o = 16; o > 0; o >>= 1) ls += __shfl_xor_sync(~0u, ls, o);
    if (lane == 0) sm[O_RED + 16 + warp] = ls;
    __syncthreads();
    if (t == 0) {
        float S = 0.f;
        #pragma unroll
        for (int w = 0; w < 16; w++) S += sm[O_RED + 16 + w];
        sm[O_XL + 0] = bown;
        sm[O_XL + 1] = S;
    }
    CLUSTER_SYNC();   // #4: logit stats
    if (t == 0) {
        float om = sm[O_XL + 0], os = sm[O_XL + 1];
        float pm = dsmem_ld(sm + O_XL + 0, peer);
        float ps = dsmem_ld(sm + O_XL + 1, peer);
        float M = fmaxf(om, pm);
        float S = os * __expf(om - M) + ps * __expf(pm - M);
        sm[O_RED + 48] = M + logf(S);
    }
    __syncthreads();
    float logZ = sm[O_RED + 48];
    float* outB = out + (size_t)b * NN + rowbase;
    for (int n = t; n < HR; n += 512) outB[n] = s_lg[n] - logZ;
    CLUSTER_SYNC();   // #5: keep smem alive until peer done reading
}

extern "C" void kernel_launch(void* const* d_in, const int* in_sizes, int n_in,
                              void* d_out, int out_size) {
    const float* emb = (const float*)d_in[0];
    const float* Wn  = (const float*)d_in[1];
    const float* Wf  = (const float*)d_in[2];
    const float* Ws  = (const float*)d_in[3];
    const float* Wo  = (const float*)d_in[4];
    const int* fidx  = (const int*)d_in[5];
    const int* lidx  = (const int*)d_in[6];
    const int* mask  = (const int*)d_in[7];
    float* out = (float*)d_out;
    cudaFuncSetAttribute(attn_v8, cudaFuncAttributeMaxDynamicSharedMemorySize, SM_WORDS * 4);
    attn_v8<<<512, 512, SM_WORDS * 4>>>(emb, Wn, Wf, Ws, Wo, fidx, lidx, mask, out);
}

// round 12
// speedup vs baseline: 1.6694x; 1.6694x over previous
#include <cuda_runtime.h>
#include <cuda_fp16.h>

#define NN 1000
#define DD 128
#define NEGV (-1e9f)
typedef unsigned long long u64;
typedef unsigned int u32;

// fp16 copy of embeddings [b][row][128 halves], written by phase 0
__device__ __align__(16) __half2 g_e16[(size_t)256 * NN * 64];

// ---- smem word offsets ----
#define O_A     0        // 18000: tile chunks (500 rows x 144B) / s_at (8000)
#define O_B     18000    // 8000: compat / p2 partials / s_lg
#define O_QT16  26000    // 528: qt fp16 [q4][d] u64, q4 stride 136 u64
#define O_GT16  26528    // 64: gt fp16, 16 uint4 granules
#define O_MEAN  26592
#define O_Q     26720
#define O_EF    26848
#define O_EL    26976
#define O_HEADS 27104
#define O_GL    27232
#define O_GT    27360
#define O_EBAR  27488    // 1024
#define O_RED   28512    // 32
#define SM_WORDS 28544   // 114176 bytes

static __device__ __forceinline__ u64 pack2(float a, float b) {
    u64 r; asm("mov.b64 %0, {%1, %2};" : "=l"(r) : "f"(a), "f"(b)); return r;
}
static __device__ __forceinline__ u64 packdup(float a) { return pack2(a, a); }
static __device__ __forceinline__ u64 fma2(u64 a, u64 b, u64 c) {
    u64 d; asm("fma.rn.f32x2 %0, %1, %2, %3;" : "=l"(d) : "l"(a), "l"(b), "l"(c)); return d;
}
static __device__ __forceinline__ float2 unpack2(u64 v) {
    float lo, hi; asm("mov.b64 {%0, %1}, %2;" : "=f"(lo), "=f"(hi) : "l"(v));
    return make_float2(lo, hi);
}
static __device__ __forceinline__ float tanh_fast(float x) {
    float y; asm("tanh.approx.f32 %0, %1;" : "=f"(y) : "f"(x)); return y;
}
static __device__ __forceinline__ __half2 h2u(u32 u) {
    return *reinterpret_cast<__half2*>(&u);
}
static __device__ __forceinline__ u32 f2h2(float a, float b) {
    __half2 h = __floats2half2_rn(a, b); return *(u32*)&h;
}
static __device__ __forceinline__ void cp16(void* dst, const void* src) {
    u32 sa = (u32)__cvta_generic_to_shared(dst);
    asm volatile("cp.async.cg.shared.global [%0], [%1], 16;" :: "r"(sa), "l"(src));
}

__global__ __launch_bounds__(512, 2) void attn_v9(
    const float* __restrict__ emb, const float* __restrict__ Wn,
    const float* __restrict__ Wf, const float* __restrict__ Ws,
    const float* __restrict__ Wo, const int* __restrict__ fidx,
    const int* __restrict__ lidx, const int* __restrict__ mask,
    float* __restrict__ out)
{
    extern __shared__ float sm[];
    const int b = blockIdx.x, t = threadIdx.x;
    const int lane = t & 31, warp = t >> 5;
    const float* embB = emb + (size_t)b * NN * DD;
    const int* mkB = mask + (size_t)b * NN;
    __half2* e16B = g_e16 + (size_t)b * (NN * 64);

    // stage chunk (R row-half, C dim-half): 500 rows x 64 dims fp16, 144B rows
    auto stage = [&](int R, int C) {
        const uint4* src = (const uint4*)e16B + (size_t)R * 500 * 16 + C * 8;
        #pragma unroll
        for (int k = 0; k < 8; k++) {
            int i = (k << 9) + t;
            if (i < 4000) {
                int row = i >> 3, seg = i & 7;
                cp16((char*)sm + row * 144 + seg * 16, src + row * 16 + seg);
            }
        }
        asm volatile("cp.async.commit_group;" ::: "memory");
    };

    // ---- Phase 0: mean partials + fp16 conversion ----
    {
        int c = t & 31, g = t >> 5;    // c: float4 col, g: 16 row groups
        const float4* E4 = (const float4*)embB + c;
        uint2* O = (uint2*)e16B + c;
        float4 acc = make_float4(0.f, 0.f, 0.f, 0.f);
        for (int k = 0; k < 63; k++) {
            int r = g + (k << 4);
            if (r < NN) {
                float4 v = E4[(size_t)r * 32];
                acc.x += v.x; acc.y += v.y; acc.z += v.z; acc.w += v.w;
                uint2 h; h.x = f2h2(v.x, v.y); h.y = f2h2(v.z, v.w);
                O[(size_t)r * 32] = h;
            }
        }
        *(float4*)(sm + O_B + g * 128 + c * 4) = acc;
    }
    if (t < DD)       sm[O_EF + t] = embB[(size_t)fidx[b] * DD + t];
    else if (t < 256) sm[O_EL + t - DD] = embB[(size_t)lidx[b] * DD + (t - DD)];
    __syncthreads();
    stage(0, 0);   // phase-1 chunk 0 in flight under the small matvecs
    if (t < DD) {
        float m = 0.f;
        #pragma unroll
        for (int g = 0; g < 16; g++) m += sm[O_B + g * 128 + t];
        sm[O_MEAN + t] = m * (1.0f / NN);
    }
    __syncthreads();

    // ---- q = mean@Wf + [ef;el]@Ws ----
    if (t < DD) {
        float acc = 0.f;
        #pragma unroll 4
        for (int i = 0; i < DD; i++) acc += sm[O_MEAN + i] * Wf[i * DD + t];
        #pragma unroll 4
        for (int i = 0; i < DD; i++) acc += sm[O_EF + i] * Ws[i * DD + t];
        #pragma unroll 4
        for (int i = 0; i < DD; i++) acc += sm[O_EL + i] * Ws[(DD + i) * DD + t];
        sm[O_Q + t] = acc;
    }
    __syncthreads();
    // ---- qt fp16 [q4][d] (4 heads per u64), scale folded ----
    if (t < 256) {
        int d = t >> 1, q4 = t & 1;
        float o[4];
        #pragma unroll
        for (int k = 0; k < 4; k++) {
            int h = q4 * 4 + k;
            const float* w = Wn + d * 384 + h * 16;
            const float* qq = sm + O_Q + h * 16;
            float acc = 0.f;
            #pragma unroll
            for (int j = 0; j < 16; j++) acc += w[j] * qq[j];
            o[k] = acc * 0.25f;
        }
        uint2* Q = (uint2*)(sm + O_QT16) + q4 * 136 + d;
        uint2 hq; hq.x = f2h2(o[0], o[1]); hq.y = f2h2(o[2], o[3]);
        *Q = hq;
    }

    // ---- Phase 1: compat, fp16 HFMA2, 2 rows x 4 heads per thread ----
    {
        const int r2 = t >> 1, q4 = t & 1;
        const bool act = r2 < 250;
        const uint4* Qb = (const uint4*)((const uint2*)(sm + O_QT16) + q4 * 136);
        __half2 a01A, a23A, a01B, a23B;
        for (int ch = 0; ch < 4; ch++) {
            int R = ch >> 1, C = ch & 1;
            if (ch > 0) { __syncthreads(); stage(R, C); }
            asm volatile("cp.async.wait_group 0;" ::: "memory");
            __syncthreads();
            if (C == 0) {
                a01A = a23A = a01B = a23B = __float2half2_rn(0.f);
            }
            if (act) {
                const uint4* rA = (const uint4*)((const char*)sm + (2 * r2) * 144);
                const uint4* rB = (const uint4*)((const char*)sm + (2 * r2 + 1) * 144);
                const uint4* Qc = Qb + C * 32;   // 64 dims = 32 uint4 (2 dims each)
                #pragma unroll
                for (int j = 0; j < 8; j++) {
                    uint4 ea = rA[j], eb = rB[j];
                    const uint4* qd = Qc + j * 4;
                    #pragma unroll
                    for (int m = 0; m < 4; m++) {
                        u32 ua = (&ea.x)[m], ub = (&eb.x)[m];
                        uint4 q = qd[m];   // h01@d0, h23@d0, h01@d1, h23@d1
                        __half2 e2a = h2u(ua), e2b = h2u(ub);
                        __half2 la = __low2half2(e2a), ha = __high2half2(e2a);
                        __half2 lb = __low2half2(e2b), hb = __high2half2(e2b);
                        a01A = __hfma2(la, h2u(q.x), a01A);
                        a23A = __hfma2(la, h2u(q.y), a23A);
                        a01A = __hfma2(ha, h2u(q.z), a01A);
                        a23A = __hfma2(ha, h2u(q.w), a23A);
                        a01B = __hfma2(lb, h2u(q.x), a01B);
                        a23B = __hfma2(lb, h2u(q.y), a23B);
                        a01B = __hfma2(hb, h2u(q.z), a01B);
                        a23B = __hfma2(hb, h2u(q.w), a23B);
                    }
                }
            }
            if (C == 1 && act) {
                int gA = R * 500 + 2 * r2, gB = gA + 1;
                int mA = mkB[gA], mB = mkB[gB];
                float2 fA01 = __half22float2(a01A), fA23 = __half22float2(a23A);
                float2 fB01 = __half22float2(a01B), fB23 = __half22float2(a23B);
                float* cpb = sm + O_B + q4 * 4000;
                cpb[0 * 1000 + gA] = mA ? NEGV : fA01.x;
                cpb[1 * 1000 + gA] = mA ? NEGV : fA01.y;
                cpb[2 * 1000 + gA] = mA ? NEGV : fA23.x;
                cpb[3 * 1000 + gA] = mA ? NEGV : fA23.y;
                cpb[0 * 1000 + gB] = mB ? NEGV : fB01.x;
                cpb[1 * 1000 + gB] = mB ? NEGV : fB01.y;
                cpb[2 * 1000 + gB] = mB ? NEGV : fB23.x;
                cpb[3 * 1000 + gB] = mB ? NEGV : fB23.y;
            }
        }
    }
    __syncthreads();

    // ---- Phase 1b: per-head softmax, 2 warps/head; attn -> s_at [n][8] fp32 ----
    {
        int h = warp >> 1, seg = warp & 1;
        const float* row = sm + O_B + h * 1000;
        float mx = -1e30f;
        for (int n = seg * 32 + lane; n < NN; n += 64) mx = fmaxf(mx, row[n]);
        #pragma unroll
        for (int o = 16; o > 0; o >>= 1) mx = fmaxf(mx, __shfl_xor_sync(~0u, mx, o));
        if (lane == 0) sm[O_RED + warp] = mx;
        __syncthreads();
        float hm = fmaxf(sm[O_RED + 2 * h], sm[O_RED + 2 * h + 1]);
        float sme = 0.f;
        for (int n = seg * 32 + lane; n < NN; n += 64) sme += __expf(row[n] - hm);
        #pragma unroll
        for (int o = 16; o > 0; o >>= 1) sme += __shfl_xor_sync(~0u, sme, o);
        if (lane == 0) sm[O_RED + 16 + warp] = sme;
        __syncthreads();
        float inv = 1.0f / (sm[O_RED + 16 + 2 * h] + sm[O_RED + 16 + 2 * h + 1]);
        for (int n = seg * 32 + lane; n < NN; n += 64)
            sm[O_A + n * 8 + h] = __expf(row[n] - hm) * inv;
    }
    __syncthreads();

    // ---- Phase 2: ebar, column reads of g_e16, MLP=8, f32x2 accum ----
    {
        int dim = t & 127, g = t >> 7;
        const __half* Eh = (const __half*)e16B + dim;
        const float* at = sm + O_A;
        u64 a0 = 0, a1 = 0, a2 = 0, a3 = 0;
        int n = g;
        for (; n + 28 < NN; n += 32) {
            float e0 = __half2float(Eh[(size_t)n * 128]);
            float e1 = __half2float(Eh[(size_t)(n + 4) * 128]);
            float e2 = __half2float(Eh[(size_t)(n + 8) * 128]);
            float e3 = __half2float(Eh[(size_t)(n + 12) * 128]);
            float e4 = __half2float(Eh[(size_t)(n + 16) * 128]);
            float e5 = __half2float(Eh[(size_t)(n + 20) * 128]);
            float e6 = __half2float(Eh[(size_t)(n + 24) * 128]);
            float e7 = __half2float(Eh[(size_t)(n + 28) * 128]);
            const u64* t0 = (const u64*)(at + n * 8);
            const u64* t1 = (const u64*)(at + (n + 4) * 8);
            const u64* t2 = (const u64*)(at + (n + 8) * 8);
            const u64* t3 = (const u64*)(at + (n + 12) * 8);
            const u64* t4 = (const u64*)(at + (n + 16) * 8);
            const u64* t5 = (const u64*)(at + (n + 20) * 8);
            const u64* t6 = (const u64*)(at + (n + 24) * 8);
            const u64* t7 = (const u64*)(at + (n + 28) * 8);
            u64 d0 = packdup(e0), d1 = packdup(e1), d2 = packdup(e2), d3 = packdup(e3);
            a0 = fma2(d0, t0[0], a0); a1 = fma2(d0, t0[1], a1);
            a2 = fma2(d0, t0[2], a2); a3 = fma2(d0, t0[3], a3);
            a0 = fma2(d1, t1[0], a0); a1 = fma2(d1, t1[1], a1);
            a2 = fma2(d1, t1[2], a2); a3 = fma2(d1, t1[3], a3);
            a0 = fma2(d2, t2[0], a0); a1 = fma2(d2, t2[1], a1);
            a2 = fma2(d2, t2[2], a2); a3 = fma2(d2, t2[3], a3);
            a0 = fma2(d3, t3[0], a0); a1 = fma2(d3, t3[1], a1);
            a2 = fma2(d3, t3[2], a2); a3 = fma2(d3, t3[3], a3);
            u64 d4 = packdup(e4), d5 = packdup(e5), d6 = packdup(e6), d7 = packdup(e7);
            a0 = fma2(d4, t4[0], a0); a1 = fma2(d4, t4[1], a1);
            a2 = fma2(d4, t4[2], a2); a3 = fma2(d4, t4[3], a3);
            a0 = fma2(d5, t5[0], a0); a1 = fma2(d5, t5[1], a1);
            a2 = fma2(d5, t5[2], a2); a3 = fma2(d5, t5[3], a3);
            a0 = fma2(d6, t6[0], a0); a1 = fma2(d6, t6[1], a1);
            a2 = fma2(d6, t6[2], a2); a3 = fma2(d6, t6[3], a3);
            a0 = fma2(d7, t7[0], a0); a1 = fma2(d7, t7[1], a1);
            a2 = fma2(d7, t7[2], a2); a3 = fma2(d7, t7[3], a3);
        }
        for (; n < NN; n += 4) {
            u64 ed = packdup(__half2float(Eh[(size_t)n * 128]));
            const u64* att = (const u64*)(at + n * 8);
            a0 = fma2(ed, att[0], a0); a1 = fma2(ed, att[1], a1);
            a2 = fma2(ed, att[2], a2); a3 = fma2(ed, att[3], a3);
        }
        __syncthreads();     // all s_at reads done; region A free
        stage(0, 0);         // prefetch phase-3 chunk 0 under the matvecs
        float2 f0 = unpack2(a0), f1 = unpack2(a1), f2 = unpack2(a2), f3 = unpack2(a3);
        float* pp = sm + O_B + g * 1024 + dim;
        pp[0] = f0.x; pp[128] = f0.y; pp[256] = f1.x; pp[384] = f1.y;
        pp[512] = f2.x; pp[640] = f2.y; pp[768] = f3.x; pp[896] = f3.y;
    }
    __syncthreads();
    {
        sm[O_EBAR + t] = (sm[O_B + t] + sm[O_B + 1024 + t])
                       + (sm[O_B + 2048 + t] + sm[O_B + 3072 + t]);
        int i2 = t + 512;
        sm[O_EBAR + i2] = (sm[O_B + i2] + sm[O_B + 1024 + i2])
                        + (sm[O_B + 2048 + i2] + sm[O_B + 3072 + i2]);
    }
    __syncthreads();

    // ---- Phase 2b: heads -> glimpse -> gtilde (+ gt16 fp16) ----
    if (t < DD) {
        int h = t >> 4;
        const float* eb = sm + O_EBAR + h * DD;
        float acc = 0.f;
        #pragma unroll 4
        for (int d = 0; d < DD; d++) acc += eb[d] * Wn[d * 384 + 128 + t];
        sm[O_HEADS + t] = acc;
    }
    __syncthreads();
    if (t < DD) {
        float acc = 0.f;
        #pragma unroll 4
        for (int i = 0; i < DD; i++) acc += sm[O_HEADS + i] * Wo[i * DD + t];
        sm[O_GL + t] = acc;
    }
    __syncthreads();
    if (t < DD) {
        const float* w = Wn + t * 384 + 256;
        float acc = 0.f;
        #pragma unroll 4
        for (int j = 0; j < DD; j++) acc += w[j] * sm[O_GL + j];
        sm[O_GT + t] = acc * 0.08838834764831845f;
    }
    __syncthreads();
    if (t < 64) ((u32*)(sm + O_GT16))[t] = f2h2(sm[O_GT + 2 * t], sm[O_GT + 2 * t + 1]);

    // ---- Phase 3: logits, fp16 HFMA2, 2 rows/thread, granule dim-split ----
    float* s_lg = sm + O_B;
    float lmax = -1e30f;
    {
        const int r2 = t >> 1, p = t & 1;
        const bool act = r2 < 250;
        const uint4* GT = (const uint4*)(sm + O_GT16);
        __half2 accA = __float2half2_rn(0.f), accB = accA;
        for (int ch = 0; ch < 4; ch++) {
            int R = ch >> 1, C = ch & 1;
            if (ch > 0) { __syncthreads(); stage(R, C); }
            asm volatile("cp.async.wait_group 0;" ::: "memory");
            __syncthreads();
            if (C == 0) { accA = __float2half2_rn(0.f); accB = accA; }
            if (act) {
                const uint4* rA = (const uint4*)((const char*)sm + (2 * r2) * 144);
                const uint4* rB = (const uint4*)((const char*)sm + (2 * r2 + 1) * 144);
                #pragma unroll
                for (int j = 0; j < 4; j++) {
                    int gseg = 2 * j + p;
                    uint4 ea = rA[gseg], eb = rB[gseg];
                    uint4 g = GT[C * 8 + gseg];
                    accA = __hfma2(h2u(ea.x), h2u(g.x), accA);
                    accA = __hfma2(h2u(ea.y), h2u(g.y), accA);
                    accA = __hfma2(h2u(ea.z), h2u(g.z), accA);
                    accA = __hfma2(h2u(ea.w), h2u(g.w), accA);
                    accB = __hfma2(h2u(eb.x), h2u(g.x), accB);
                    accB = __hfma2(h2u(eb.y), h2u(g.y), accB);
                    accB = __hfma2(h2u(eb.z), h2u(g.z), accB);
                    accB = __hfma2(h2u(eb.w), h2u(g.w), accB);
                }
            }
            if (C == 1) {
                float2 fa = __half22float2(accA), fb = __half22float2(accB);
                float sA = fa.x + fa.y, sB = fb.x + fb.y;
                sA += __shfl_xor_sync(~0u, sA, 1);
                sB += __shfl_xor_sync(~0u, sB, 1);
                if (p == 0 && act) {
                    int gA = R * 500 + 2 * r2, gB = gA + 1;
                    float vA = tanh_fast(sA) * 10.0f;
                    float vB = tanh_fast(sB) * 10.0f;
                    if (mkB[gA]) vA = NEGV;
                    if (mkB[gB]) vB = NEGV;
                    s_lg[gA] = vA; s_lg[gB] = vB;
                    lmax = fmaxf(lmax, fmaxf(vA, vB));
                }
            }
        }
    }
    __syncthreads();
    // ---- log-softmax over 1000 ----
    #pragma unroll
    for (int o = 16; o > 0; o >>= 1) lmax = fmaxf(lmax, __shfl_xor_sync(~0u, lmax, o));
    if (lane == 0) sm[O_RED + warp] = lmax;
    __syncthreads();
    float bmax = sm[O_RED + 0];
    #pragma unroll
    for (int w = 1; w < 16; w++) bmax = fmaxf(bmax, sm[O_RED + w]);
    float ls = 0.f;
    for (int n = t; n < NN; n += 512) ls += __expf(s_lg[n] - bmax);
    #pragma unroll
    for (int o = 16; o > 0; o >>= 1) ls += __shfl_xor_sync(~0u, ls, o);
    if (lane == 0) sm[O_RED + 16 + warp] = ls;
    __syncthreads();
    float tot = sm[O_RED + 16];
    #pragma unroll
    for (int w = 1; w < 16; w++) tot += sm[O_RED + 16 + w];
    float logZ = bmax + logf(tot);
    float* outB = out + (size_t)b * NN;
    for (int n = t; n < NN; n += 512) outB[n] = s_lg[n] - logZ;
}

extern "C" void kernel_launch(void* const* d_in, const int* in_sizes, int n_in,
                              void* d_out, int out_size) {
    const float* emb = (const float*)d_in[0];
    const float* Wn  = (const float*)d_in[1];
    const float* Wf  = (const float*)d_in[2];
    const float* Ws  = (const float*)d_in[3];
    const float* Wo  = (const float*)d_in[4];
    const int* fidx  = (const int*)d_in[5];
    const int* lidx  = (const int*)d_in[6];
    const int* mask  = (const int*)d_in[7];
    float* out = (float*)d_out;
    cudaFuncSetAttribute(attn_v9, cudaFuncAttributeMaxDynamicSharedMemorySize, SM_WORDS * 4);
    attn_v9<<<256, 512, SM_WORDS * 4>>>(emb, Wn, Wf, Ws, Wo, fidx, lidx, mask, out);
}

// round 13
// speedup vs baseline: 1.7847x; 1.0691x over previous
#include <cuda_runtime.h>
#include <cuda_fp16.h>

#define NN 1000
#define DD 128
#define NEGV (-1e9f)
typedef unsigned long long u64;
typedef unsigned int u32;

// fp16 copy of embeddings [b][row][128 halves], written by phase 0
__device__ __align__(16) __half2 g_e16[(size_t)256 * NN * 64];

// ---- smem word offsets ----
#define O_A     0        // 18432: chunk buffer 512 rows x 144B
#define O_AT    18432    // 4128: s_atT fp16 [8][1032]
#define O_C     22560    // 4096: compat fp16 [8][1024] / s_p f32 [2][8][16][8] + ebar / s_lg
#define O_QT    26656    // 544: qtT fp16 [8][136]
#define O_GT16  27200    // 64: gt fp16 [128]
#define O_S0    27264    // 128: mean / heads
#define O_S1    27392    // 128: q / gl
#define O_S2    27520    // 128: ef / gt
#define O_S3    27648    // 128: el
#define O_RED   27776    // 32
#define SM_WORDS 27808   // 111232 bytes

static __device__ __forceinline__ float tanh_fast(float x) {
    float y; asm("tanh.approx.f32 %0, %1;" : "=f"(y) : "f"(x)); return y;
}
static __device__ __forceinline__ u32 f2h2(float a, float b) {
    __half2 h = __floats2half2_rn(a, b); return *(u32*)&h;
}
static __device__ __forceinline__ void cp16(void* dst, const void* src) {
    u32 sa = (u32)__cvta_generic_to_shared(dst);
    asm volatile("cp.async.cg.shared.global [%0], [%1], 16;" :: "r"(sa), "l"(src));
}
static __device__ __forceinline__ void mma16816(float* c, u32 a0, u32 a1, u32 a2, u32 a3,
                                                u32 b0, u32 b1) {
    asm volatile("mma.sync.aligned.m16n8k16.row.col.f32.f16.f16.f32 "
        "{%0,%1,%2,%3},{%4,%5,%6,%7},{%8,%9},{%0,%1,%2,%3};"
        : "+f"(c[0]), "+f"(c[1]), "+f"(c[2]), "+f"(c[3])
        : "r"(a0), "r"(a1), "r"(a2), "r"(a3), "r"(b0), "r"(b1));
}
static __device__ __forceinline__ void ldsm4(u32 addr, u32& a0, u32& a1, u32& a2, u32& a3) {
    asm volatile("ldmatrix.sync.aligned.m8n8.x4.shared.b16 {%0,%1,%2,%3},[%4];"
        : "=r"(a0), "=r"(a1), "=r"(a2), "=r"(a3) : "r"(addr));
}
static __device__ __forceinline__ void ldsm4t(u32 addr, u32& a0, u32& a1, u32& a2, u32& a3) {
    asm volatile("ldmatrix.sync.aligned.m8n8.x4.trans.shared.b16 {%0,%1,%2,%3},[%4];"
        : "=r"(a0), "=r"(a1), "=r"(a2), "=r"(a3) : "r"(addr));
}

__global__ __launch_bounds__(512, 2) void attn_v10(
    const float* __restrict__ emb, const float* __restrict__ Wn,
    const float* __restrict__ Wf, const float* __restrict__ Ws,
    const float* __restrict__ Wo, const int* __restrict__ fidx,
    const int* __restrict__ lidx, const int* __restrict__ mask,
    float* __restrict__ out)
{
    extern __shared__ float sm[];
    __half* smh = (__half*)sm;
    const int b = blockIdx.x, t = threadIdx.x;
    const int lane = t & 31, warp = t >> 5;
    const float* embB = emb + (size_t)b * NN * DD;
    const int* mkB = mask + (size_t)b * NN;
    __half2* e16B = g_e16 + (size_t)b * (NN * 64);
    const u32 sbase = (u32)__cvta_generic_to_shared(sm);

    // stage chunk (R row-half of 512, C dim-half of 64) into region A
    auto stage = [&](int R, int C) {
        const uint4* src = (const uint4*)e16B + C * 8;
        #pragma unroll
        for (int k = 0; k < 8; k++) {
            int i = (k << 9) + t;
            int rl = i >> 3, seg = i & 7;
            int gr = R * 512 + rl; if (gr > NN - 1) gr = NN - 1;
            cp16((char*)sm + rl * 144 + seg * 16, src + (size_t)gr * 16 + seg);
        }
        asm volatile("cp.async.commit_group;" ::: "memory");
    };

    // ---- Phase 0: mean partials (in O_C) + fp16 conversion, MLP=4 ----
    {
        int c = t & 31, g = t >> 5;
        const float4* E4 = (const float4*)embB + c;
        uint2* O = (uint2*)e16B + c;
        float sx = 0, sy = 0, sz = 0, sw = 0;
        int k = 0;
        for (; k < 60; k += 4) {
            int r0 = g + (k << 4), r1 = r0 + 16, r2 = r0 + 32, r3 = r0 + 48;
            float4 v0 = E4[(size_t)r0 * 32], v1 = E4[(size_t)r1 * 32];
            float4 v2 = E4[(size_t)r2 * 32], v3 = E4[(size_t)r3 * 32];
            uint2 h;
            h.x = f2h2(v0.x, v0.y); h.y = f2h2(v0.z, v0.w); O[(size_t)r0 * 32] = h;
            h.x = f2h2(v1.x, v1.y); h.y = f2h2(v1.z, v1.w); O[(size_t)r1 * 32] = h;
            h.x = f2h2(v2.x, v2.y); h.y = f2h2(v2.z, v2.w); O[(size_t)r2 * 32] = h;
            h.x = f2h2(v3.x, v3.y); h.y = f2h2(v3.z, v3.w); O[(size_t)r3 * 32] = h;
            sx += (v0.x + v1.x) + (v2.x + v3.x);
            sy += (v0.y + v1.y) + (v2.y + v3.y);
            sz += (v0.z + v1.z) + (v2.z + v3.z);
            sw += (v0.w + v1.w) + (v2.w + v3.w);
        }
        for (; k < 63; k++) {
            int r = g + (k << 4);
            if (r < NN) {
                float4 v = E4[(size_t)r * 32];
                uint2 h; h.x = f2h2(v.x, v.y); h.y = f2h2(v.z, v.w);
                O[(size_t)r * 32] = h;
                sx += v.x; sy += v.y; sz += v.z; sw += v.w;
            }
        }
        *(float4*)(sm + O_C + g * 128 + c * 4) = make_float4(sx, sy, sz, sw);
    }
    if (t < 128)      sm[O_S2 + t] = embB[(size_t)fidx[b] * DD + t];
    else if (t < 256) sm[O_S3 + t - 128] = embB[(size_t)lidx[b] * DD + (t - 128)];
    __syncthreads();
    stage(0, 0);   // prefetch P1 chunk 0 (region A is free)
    if (t < 128) {
        float m = 0.f;
        #pragma unroll
        for (int g = 0; g < 16; g++) m += sm[O_C + g * 128 + t];
        sm[O_S0 + t] = m * (1.0f / NN);
    }
    __syncthreads();
    // q = mean@Wf + [ef;el]@Ws
    if (t < 128) {
        float acc = 0.f;
        #pragma unroll 4
        for (int i = 0; i < DD; i++) acc += sm[O_S0 + i] * Wf[i * DD + t];
        #pragma unroll 4
        for (int i = 0; i < DD; i++) acc += sm[O_S2 + i] * Ws[i * DD + t];
        #pragma unroll 4
        for (int i = 0; i < DD; i++) acc += sm[O_S3 + i] * Ws[(DD + i) * DD + t];
        sm[O_S1 + t] = acc;
    }
    __syncthreads();
    // qtT fp16 [head][dim], stride 136, scale folded
    if (t < 256) {
        int d = t >> 1, q4 = t & 1;
        #pragma unroll
        for (int kk = 0; kk < 4; kk++) {
            int h = q4 * 4 + kk;
            const float* w = Wn + d * 384 + h * 16;
            const float* qq = sm + O_S1 + h * 16;
            float acc = 0.f;
            #pragma unroll
            for (int j = 0; j < 16; j++) acc += w[j] * qq[j];
            smh[2 * O_QT + h * 136 + d] = __float2half(acc * 0.25f);
        }
    }

    // ---- Phase 1: compat via mma. Warp owns M-tiles (warp, warp+16) per R-half ----
    {
        float cf[2][4];
        const int g = lane >> 2, tc = lane & 3;
        for (int ch = 0; ch < 4; ch++) {
            int R = ch >> 1, C = ch & 1;
            if (ch > 0) { __syncthreads(); stage(R, C); }
            asm volatile("cp.async.wait_group 0;" ::: "memory");
            __syncthreads();
            if (C == 0) {
                #pragma unroll
                for (int i = 0; i < 4; i++) { cf[0][i] = 0.f; cf[1][i] = 0.f; }
            }
            #pragma unroll
            for (int kl = 0; kl < 4; kl++) {
                int kb = C * 64 + kl * 16;
                u32 b0 = *(const u32*)(smh + 2 * O_QT + (lane >> 2) * 136 + kb + 2 * (lane & 3));
                u32 b1 = *(const u32*)(smh + 2 * O_QT + (lane >> 2) * 136 + kb + 2 * (lane & 3) + 8);
                #pragma unroll
                for (int mt = 0; mt < 2; mt++) {
                    int tile = warp + 16 * mt;
                    u32 addr = sbase + (u32)((tile * 16 + (lane & 15)) * 144 + (lane >> 4) * 16 + kl * 32);
                    u32 a0, a1, a2, a3;
                    ldsm4(addr, a0, a1, a2, a3);
                    mma16816(cf[mt], a0, a1, a2, a3, b0, b1);
                }
            }
            if (C == 1) {
                __half* cp = smh + 2 * O_C;
                #pragma unroll
                for (int mt = 0; mt < 2; mt++) {
                    int r0 = R * 512 + (warp + 16 * mt) * 16 + g;
                    int r1 = r0 + 8;
                    if (r0 < NN) {
                        cp[(2 * tc) * 1024 + r0]     = __float2half(cf[mt][0]);
                        cp[(2 * tc + 1) * 1024 + r0] = __float2half(cf[mt][1]);
                    }
                    if (r1 < NN) {
                        cp[(2 * tc) * 1024 + r1]     = __float2half(cf[mt][2]);
                        cp[(2 * tc + 1) * 1024 + r1] = __float2half(cf[mt][3]);
                    }
                }
            }
        }
    }
    __syncthreads();
    stage(0, 0);   // prefetch P2 chunk 0 (softmax uses other regions)

    // ---- Phase 1b: per-head softmax (2 warps/head), mask applied here ----
    {
        int h = warp >> 1, seg = warp & 1;
        const __half* row = smh + 2 * O_C + h * 1024;
        float mx = -1e30f;
        for (int n = seg * 32 + lane; n < NN; n += 64) {
            float v = mkB[n] ? -1e30f : __half2float(row[n]);
            mx = fmaxf(mx, v);
        }
        #pragma unroll
        for (int o = 16; o > 0; o >>= 1) mx = fmaxf(mx, __shfl_xor_sync(~0u, mx, o));
        if (lane == 0) sm[O_RED + warp] = mx;
        __syncthreads();
        float hm = fmaxf(sm[O_RED + 2 * h], sm[O_RED + 2 * h + 1]);
        float sme = 0.f;
        for (int n = seg * 32 + lane; n < NN; n += 64) {
            float v = mkB[n] ? -1e30f : __half2float(row[n]);
            sme += __expf(v - hm);
        }
        #pragma unroll
        for (int o = 16; o > 0; o >>= 1) sme += __shfl_xor_sync(~0u, sme, o);
        if (lane == 0) sm[O_RED + 16 + warp] = sme;
        __syncthreads();
        float inv = 1.0f / (sm[O_RED + 16 + 2 * h] + sm[O_RED + 16 + 2 * h + 1]);
        __half* at = smh + 2 * O_AT + h * 1032;
        for (int n = seg * 32 + lane; n < NN; n += 64) {
            float v = mkB[n] ? -1e30f : __half2float(row[n]);
            at[n] = __float2half(__expf(v - hm) * inv);
        }
    }
    if (t < 128) {   // zero attn pad rows 1000..1031
        int h = t >> 4, i = 1000 + (t & 15) * 2;
        *(u32*)(smh + 2 * O_AT + h * 1032 + i) = 0;
    }
    __syncthreads();

    // ---- Phase 2: ebar = attn^T-weighted sum via mma with ldmatrix.trans ----
    {
        int m = warp & 7, kh = warp >> 3;
        float cf[4] = {0.f, 0.f, 0.f, 0.f};
        for (int ch = 0; ch < 4; ch++) {
            int R = ch >> 1, C = ch & 1;
            if (ch > 0) { __syncthreads(); stage(R, C); }
            asm volatile("cp.async.wait_group 0;" ::: "memory");
            __syncthreads();
            if ((m >> 2) == C) {
                int srow = (lane & 7) + ((lane >> 4) & 1) * 8;
                int doff = ((lane >> 3) & 1) * 16 + (m & 3) * 32;
                const __half* atp = smh + 2 * O_AT + (lane >> 2) * 1032 + 2 * (lane & 3);
                #pragma unroll
                for (int kt = 0; kt < 16; kt++) {
                    int klocal = kh * 16 + kt;
                    int rb = R * 512 + klocal * 16;
                    u32 b0 = *(const u32*)(atp + rb);
                    u32 b1 = *(const u32*)(atp + rb + 8);
                    u32 addr = sbase + (u32)((klocal * 16 + srow) * 144 + doff);
                    u32 a0, a1, a2, a3;
                    ldsm4t(addr, a0, a1, a2, a3);
                    mma16816(cf, a0, a1, a2, a3, b0, b1);
                }
            }
        }
        __syncthreads();
        stage(0, 0);   // prefetch P3 chunk 0
        // store partial frags to s_p [kh][m][16][8] f32 at O_C
        int g = lane >> 2, tc = lane & 3;
        float* sp = sm + O_C;
        *(float2*)(sp + ((kh * 8 + m) * 16 + g) * 8 + 2 * tc)       = make_float2(cf[0], cf[1]);
        *(float2*)(sp + ((kh * 8 + m) * 16 + g + 8) * 8 + 2 * tc)   = make_float2(cf[2], cf[3]);
    }
    __syncthreads();
    // ebar[h][d] at O_C+2048
    for (int i = t; i < 1024; i += 512) {
        int h = i >> 7, d = i & 127, m2 = d >> 4, g2 = d & 15;
        sm[O_C + 2048 + i] = sm[O_C + (m2 * 16 + g2) * 8 + h]
                           + sm[O_C + ((8 + m2) * 16 + g2) * 8 + h];
    }
    __syncthreads();

    // ---- Phase 2b: heads -> glimpse -> gtilde (+ gt16) ----
    if (t < 128) {
        int h = t >> 4;
        const float* eb = sm + O_C + 2048 + h * 128;
        float acc = 0.f;
        #pragma unroll 4
        for (int d = 0; d < DD; d++) acc += eb[d] * Wn[d * 384 + 128 + t];
        sm[O_S0 + t] = acc;
    }
    __syncthreads();
    if (t < 128) {
        float acc = 0.f;
        #pragma unroll 4
        for (int i = 0; i < DD; i++) acc += sm[O_S0 + i] * Wo[i * DD + t];
        sm[O_S1 + t] = acc;
    }
    __syncthreads();
    if (t < 128) {
        const float* w = Wn + t * 384 + 256;
        float acc = 0.f;
        #pragma unroll 4
        for (int j = 0; j < DD; j++) acc += w[j] * sm[O_S1 + j];
        sm[O_S2 + t] = acc * 0.08838834764831845f;
    }
    __syncthreads();
    if (t < 64) ((u32*)(sm + O_GT16))[t] = f2h2(sm[O_S2 + 2 * t], sm[O_S2 + 2 * t + 1]);

    // ---- Phase 3: logits via mma (gt in B column 0) ----
    float* s_lg = sm + O_C;
    float lmax = -1e30f;
    {
        float cf[2][4];
        const int g = lane >> 2;
        for (int ch = 0; ch < 4; ch++) {
            int R = ch >> 1, C = ch & 1;
            if (ch > 0) { __syncthreads(); stage(R, C); }
            asm volatile("cp.async.wait_group 0;" ::: "memory");
            __syncthreads();
            if (C == 0) {
                #pragma unroll
                for (int i = 0; i < 4; i++) { cf[0][i] = 0.f; cf[1][i] = 0.f; }
            }
            #pragma unroll
            for (int kl = 0; kl < 4; kl++) {
                int kb = C * 64 + kl * 16;
                u32 b0 = 0, b1 = 0;
                if (lane < 4) {
                    b0 = *(const u32*)(smh + 2 * O_GT16 + kb + 2 * lane);
                    b1 = *(const u32*)(smh + 2 * O_GT16 + kb + 2 * lane + 8);
                }
                #pragma unroll
                for (int mt = 0; mt < 2; mt++) {
                    int tile = warp + 16 * mt;
                    u32 addr = sbase + (u32)((tile * 16 + (lane & 15)) * 144 + (lane >> 4) * 16 + kl * 32);
                    u32 a0, a1, a2, a3;
                    ldsm4(addr, a0, a1, a2, a3);
                    mma16816(cf[mt], a0, a1, a2, a3, b0, b1);
                }
            }
            if (C == 1 && (lane & 3) == 0) {
                #pragma unroll
                for (int mt = 0; mt < 2; mt++) {
                    int r0 = R * 512 + (warp + 16 * mt) * 16 + g;
                    int r1 = r0 + 8;
                    if (r0 < NN) {
                        float v = tanh_fast(cf[mt][0]) * 10.0f;
                        if (mkB[r0]) v = NEGV;
                        s_lg[r0] = v; lmax = fmaxf(lmax, v);
                    }
                    if (r1 < NN) {
                        float v = tanh_fast(cf[mt][2]) * 10.0f;
                        if (mkB[r1]) v = NEGV;
                        s_lg[r1] = v; lmax = fmaxf(lmax, v);
                    }
                }
            }
        }
    }
    __syncthreads();
    // ---- log-softmax over 1000 ----
    #pragma unroll
    for (int o = 16; o > 0; o >>= 1) lmax = fmaxf(lmax, __shfl_xor_sync(~0u, lmax, o));
    if (lane == 0) sm[O_RED + warp] = lmax;
    __syncthreads();
    float bmax = sm[O_RED + 0];
    #pragma unroll
    for (int w = 1; w < 16; w++) bmax = fmaxf(bmax, sm[O_RED + w]);
    float ls = 0.f;
    for (int n = t; n < NN; n += 512) ls += __expf(s_lg[n] - bmax);
    #pragma unroll
    for (int o = 16; o > 0; o >>= 1) ls += __shfl_xor_sync(~0u, ls, o);
    if (lane == 0) sm[O_RED + 16 + warp] = ls;
    __syncthreads();
    float tot = sm[O_RED + 16];
    #pragma unroll
    for (int w = 1; w < 16; w++) tot += sm[O_RED + 16 + w];
    float logZ = bmax + logf(tot);
    float* outB = out + (size_t)b * NN;
    for (int n = t; n < NN; n += 512) outB[n] = s_lg[n] - logZ;
}

extern "C" void kernel_launch(void* const* d_in, const int* in_sizes, int n_in,
                              void* d_out, int out_size) {
    const float* emb = (const float*)d_in[0];
    const float* Wn  = (const float*)d_in[1];
    const float* Wf  = (const float*)d_in[2];
    const float* Ws  = (const float*)d_in[3];
    const float* Wo  = (const float*)d_in[4];
    const int* fidx  = (const int*)d_in[5];
    const int* lidx  = (const int*)d_in[6];
    const int* mask  = (const int*)d_in[7];
    float* out = (float*)d_out;
    cudaFuncSetAttribute(attn_v10, cudaFuncAttributeMaxDynamicSharedMemorySize, SM_WORDS * 4);
    attn_v10<<<256, 512, SM_WORDS * 4>>>(emb, Wn, Wf, Ws, Wo, fidx, lidx, mask, out);
}

// round 14
// speedup vs baseline: 2.0800x; 1.1655x over previous
#include <cuda_runtime.h>
#include <cuda_fp16.h>

#define NN 1000
#define DD 128
#define NEGV (-1e9f)
typedef unsigned long long u64;
typedef unsigned int u32;

// fp16 copy of embeddings [b][row][128 halves], written by phase 0
__device__ __align__(16) __half2 g_e16[(size_t)256 * NN * 64];

// ---- smem word offsets ----
#define O_A     0        // 18432: two 36864B chunk buffers (256 rows x 144B each)
#define O_AT    18432    // 4128: s_atT fp16 [8][1032]
#define O_C     22560    // 4096: compat fp16 [8][1024] / s_p f32 / ebar / s_lg
#define O_QT    26656    // 544: qtT fp16 [8][136]
#define O_GT16  27200    // 64: gt fp16 [128]
#define O_S0    27264    // 128: mean / heads
#define O_S1    27392    // 128: q / gl
#define O_S2    27520    // 128: ef / gt
#define O_S3    27648    // 128: el
#define O_RED   27776    // 32
#define SM_WORDS 27808   // 111232 bytes

static __device__ __forceinline__ float tanh_fast(float x) {
    float y; asm("tanh.approx.f32 %0, %1;" : "=f"(y) : "f"(x)); return y;
}
static __device__ __forceinline__ u32 f2h2(float a, float b) {
    __half2 h = __floats2half2_rn(a, b); return *(u32*)&h;
}
static __device__ __forceinline__ void cp16(void* dst, const void* src) {
    u32 sa = (u32)__cvta_generic_to_shared(dst);
    asm volatile("cp.async.cg.shared.global [%0], [%1], 16;" :: "r"(sa), "l"(src));
}
static __device__ __forceinline__ void mma16816(float* c, u32 a0, u32 a1, u32 a2, u32 a3,
                                                u32 b0, u32 b1) {
    asm volatile("mma.sync.aligned.m16n8k16.row.col.f32.f16.f16.f32 "
        "{%0,%1,%2,%3},{%4,%5,%6,%7},{%8,%9},{%0,%1,%2,%3};"
        : "+f"(c[0]), "+f"(c[1]), "+f"(c[2]), "+f"(c[3])
        : "r"(a0), "r"(a1), "r"(a2), "r"(a3), "r"(b0), "r"(b1));
}
static __device__ __forceinline__ void ldsm4(u32 addr, u32& a0, u32& a1, u32& a2, u32& a3) {
    asm volatile("ldmatrix.sync.aligned.m8n8.x4.shared.b16 {%0,%1,%2,%3},[%4];"
        : "=r"(a0), "=r"(a1), "=r"(a2), "=r"(a3) : "r"(addr));
}
static __device__ __forceinline__ void ldsm4t(u32 addr, u32& a0, u32& a1, u32& a2, u32& a3) {
    asm volatile("ldmatrix.sync.aligned.m8n8.x4.trans.shared.b16 {%0,%1,%2,%3},[%4];"
        : "=r"(a0), "=r"(a1), "=r"(a2), "=r"(a3) : "r"(addr));
}

__global__ __launch_bounds__(512, 2) void attn_v11(
    const float* __restrict__ emb, const float* __restrict__ Wn,
    const float* __restrict__ Wf, const float* __restrict__ Ws,
    const float* __restrict__ Wo, const int* __restrict__ fidx,
    const int* __restrict__ lidx, const int* __restrict__ mask,
    float* __restrict__ out)
{
    extern __shared__ float sm[];
    __half* smh = (__half*)sm;
    const int b = blockIdx.x, t = threadIdx.x;
    const int lane = t & 31, warp = t >> 5;
    const float* embB = emb + (size_t)b * NN * DD;
    const int* mkB = mask + (size_t)b * NN;
    __half2* e16B = g_e16 + (size_t)b * (NN * 64);
    const u32 sbase = (u32)__cvta_generic_to_shared(sm);

    // chunk ch: R = ch>>1 (256-row quarter), C = ch&1 (64-dim half); buf = ch&1
    auto stage = [&](int ch) {
        int R = (ch >> 1) & 3, C = ch & 1;
        char* dstb = (char*)sm + (ch & 1) * 36864;
        const uint4* src = (const uint4*)e16B + C * 8;
        #pragma unroll
        for (int k = 0; k < 4; k++) {
            int i = (k << 9) + t;
            int rl = i >> 3, seg = i & 7;
            int gr = R * 256 + rl; if (gr > NN - 1) gr = NN - 1;
            cp16(dstb + rl * 144 + seg * 16, src + (size_t)gr * 16 + seg);
        }
        asm volatile("cp.async.commit_group;" ::: "memory");
    };

    // ---- Phase 0: mean partials (in O_C) + fp16 conversion, MLP=4 ----
    {
        int c = t & 31, g = t >> 5;
        const float4* E4 = (const float4*)embB + c;
        uint2* O = (uint2*)e16B + c;
        float sx = 0, sy = 0, sz = 0, sw = 0;
        int k = 0;
        for (; k < 60; k += 4) {
            int r0 = g + (k << 4), r1 = r0 + 16, r2 = r0 + 32, r3 = r0 + 48;
            float4 v0 = E4[(size_t)r0 * 32], v1 = E4[(size_t)r1 * 32];
            float4 v2 = E4[(size_t)r2 * 32], v3 = E4[(size_t)r3 * 32];
            uint2 h;
            h.x = f2h2(v0.x, v0.y); h.y = f2h2(v0.z, v0.w); O[(size_t)r0 * 32] = h;
            h.x = f2h2(v1.x, v1.y); h.y = f2h2(v1.z, v1.w); O[(size_t)r1 * 32] = h;
            h.x = f2h2(v2.x, v2.y); h.y = f2h2(v2.z, v2.w); O[(size_t)r2 * 32] = h;
            h.x = f2h2(v3.x, v3.y); h.y = f2h2(v3.z, v3.w); O[(size_t)r3 * 32] = h;
            sx += (v0.x + v1.x) + (v2.x + v3.x);
            sy += (v0.y + v1.y) + (v2.y + v3.y);
            sz += (v0.z + v1.z) + (v2.z + v3.z);
            sw += (v0.w + v1.w) + (v2.w + v3.w);
        }
        for (; k < 63; k++) {
            int r = g + (k << 4);
            if (r < NN) {
                float4 v = E4[(size_t)r * 32];
                uint2 h; h.x = f2h2(v.x, v.y); h.y = f2h2(v.z, v.w);
                O[(size_t)r * 32] = h;
                sx += v.x; sy += v.y; sz += v.z; sw += v.w;
            }
        }
        *(float4*)(sm + O_C + g * 128 + c * 4) = make_float4(sx, sy, sz, sw);
    }
    if (t < 128)      sm[O_S2 + t] = embB[(size_t)fidx[b] * DD + t];
    else if (t < 256) sm[O_S3 + t - 128] = embB[(size_t)lidx[b] * DD + (t - 128)];
    __syncthreads();
    stage(0);   // P1 chunk 0 in flight under mean/q/qt
    if (t < 128) {
        float m = 0.f;
        #pragma unroll
        for (int g = 0; g < 16; g++) m += sm[O_C + g * 128 + t];
        sm[O_S0 + t] = m * (1.0f / NN);
    }
    __syncthreads();
    // q = mean@Wf + [ef;el]@Ws (2-way split accumulators)
    if (t < 128) {
        float a0 = 0.f, a1 = 0.f;
        #pragma unroll 4
        for (int i = 0; i < DD; i += 2) {
            a0 += sm[O_S0 + i] * Wf[i * DD + t];
            a1 += sm[O_S0 + i + 1] * Wf[(i + 1) * DD + t];
        }
        #pragma unroll 4
        for (int i = 0; i < DD; i += 2) {
            a0 += sm[O_S2 + i] * Ws[i * DD + t];
            a1 += sm[O_S2 + i + 1] * Ws[(i + 1) * DD + t];
        }
        #pragma unroll 4
        for (int i = 0; i < DD; i += 2) {
            a0 += sm[O_S3 + i] * Ws[(DD + i) * DD + t];
            a1 += sm[O_S3 + i + 1] * Ws[(DD + i + 1) * DD + t];
        }
        sm[O_S1 + t] = a0 + a1;
    }
    __syncthreads();
    // qtT fp16 [head][dim], stride 136, scale folded
    if (t < 256) {
        int d = t >> 1, q4 = t & 1;
        #pragma unroll
        for (int kk = 0; kk < 4; kk++) {
            int h = q4 * 4 + kk;
            const float* w = Wn + d * 384 + h * 16;
            const float* qq = sm + O_S1 + h * 16;
            float acc = 0.f;
            #pragma unroll
            for (int j = 0; j < 16; j++) acc += w[j] * qq[j];
            smh[2 * O_QT + h * 136 + d] = __float2half(acc * 0.25f);
        }
    }

    // ---- Phase 1: compat via mma, double-buffered; warp owns 1 M-tile/chunk ----
    {
        float cf[4];
        const int g = lane >> 2, tc = lane & 3, hq = lane >> 2;
        for (int ch = 0; ch < 8; ch++) {
            int R = ch >> 1, C = ch & 1;
            if (ch + 1 < 8) {
                stage(ch + 1);
                asm volatile("cp.async.wait_group 1;" ::: "memory");
            } else {
                asm volatile("cp.async.wait_group 0;" ::: "memory");
            }
            __syncthreads();
            if (C == 0) { cf[0] = cf[1] = cf[2] = cf[3] = 0.f; }
            const u32 bufb = sbase + (u32)((ch & 1) * 36864);
            #pragma unroll
            for (int kl = 0; kl < 4; kl++) {
                int kb = C * 64 + kl * 16;
                u32 b0 = *(const u32*)(smh + 2 * O_QT + hq * 136 + kb + 2 * tc);
                u32 b1 = *(const u32*)(smh + 2 * O_QT + hq * 136 + kb + 2 * tc + 8);
                u32 addr = bufb + (u32)((warp * 16 + (lane & 15)) * 144 + (lane >> 4) * 16 + kl * 32);
                u32 a0, a1, a2, a3;
                ldsm4(addr, a0, a1, a2, a3);
                mma16816(cf, a0, a1, a2, a3, b0, b1);
            }
            if (C == 1) {
                __half* cp = smh + 2 * O_C;
                int r0 = R * 256 + warp * 16 + g, r1 = r0 + 8;
                if (r0 < NN) {
                    cp[(2 * tc) * 1024 + r0]     = __float2half(cf[0]);
                    cp[(2 * tc + 1) * 1024 + r0] = __float2half(cf[1]);
                }
                if (r1 < NN) {
                    cp[(2 * tc) * 1024 + r1]     = __float2half(cf[2]);
                    cp[(2 * tc + 1) * 1024 + r1] = __float2half(cf[3]);
                }
            }
            __syncthreads();
        }
    }
    stage(0);   // prefetch P2 chunk 0 under the softmax

    // ---- Phase 1b: per-head softmax (2 warps/head), mask applied here ----
    {
        int h = warp >> 1, seg = warp & 1;
        const __half* row = smh + 2 * O_C + h * 1024;
        float mx = -1e30f;
        for (int n = seg * 32 + lane; n < NN; n += 64) {
            float v = mkB[n] ? -1e30f : __half2float(row[n]);
            mx = fmaxf(mx, v);
        }
        #pragma unroll
        for (int o = 16; o > 0; o >>= 1) mx = fmaxf(mx, __shfl_xor_sync(~0u, mx, o));
        if (lane == 0) sm[O_RED + warp] = mx;
        __syncthreads();
        float hm = fmaxf(sm[O_RED + 2 * h], sm[O_RED + 2 * h + 1]);
        float sme = 0.f;
        for (int n = seg * 32 + lane; n < NN; n += 64) {
            float v = mkB[n] ? -1e30f : __half2float(row[n]);
            sme += __expf(v - hm);
        }
        #pragma unroll
        for (int o = 16; o > 0; o >>= 1) sme += __shfl_xor_sync(~0u, sme, o);
        if (lane == 0) sm[O_RED + 16 + warp] = sme;
        __syncthreads();
        float inv = 1.0f / (sm[O_RED + 16 + 2 * h] + sm[O_RED + 16 + 2 * h + 1]);
        __half* at = smh + 2 * O_AT + h * 1032;
        for (int n = seg * 32 + lane; n < NN; n += 64) {
            float v = mkB[n] ? -1e30f : __half2float(row[n]);
            at[n] = __float2half(__expf(v - hm) * inv);
        }
    }
    if (t < 128) {   // zero attn pad rows 1000..1031
        int h = t >> 4, i = 1000 + (t & 15) * 2;
        *(u32*)(smh + 2 * O_AT + h * 1032 + i) = 0;
    }
    __syncthreads();

    // ---- Phase 2: ebar via mma + ldmatrix.trans, double-buffered ----
    {
        int m = warp & 7, kh = warp >> 3;
        float cf[4] = {0.f, 0.f, 0.f, 0.f};
        int srow = (lane & 7) + ((lane >> 4) & 1) * 8;
        int doff = ((lane >> 3) & 1) * 16 + (m & 3) * 32;
        const __half* atp = smh + 2 * O_AT + (lane >> 2) * 1032 + 2 * (lane & 3);
        for (int ch = 0; ch < 8; ch++) {
            int R = ch >> 1, C = ch & 1;
            if (ch + 1 < 8) {
                stage(ch + 1);
                asm volatile("cp.async.wait_group 1;" ::: "memory");
            } else {
                asm volatile("cp.async.wait_group 0;" ::: "memory");
            }
            __syncthreads();
            if ((m >> 2) == C) {
                const u32 bufb = sbase + (u32)((ch & 1) * 36864);
                #pragma unroll
                for (int kt = 0; kt < 8; kt++) {
                    int klocal = kh * 8 + kt;          // ktile within chunk (16 total)
                    int rb = R * 256 + klocal * 16;    // global row base
                    u32 b0 = *(const u32*)(atp + rb);
                    u32 b1 = *(const u32*)(atp + rb + 8);
                    u32 addr = bufb + (u32)((klocal * 16 + srow) * 144 + doff);
                    u32 a0, a1, a2, a3;
                    ldsm4t(addr, a0, a1, a2, a3);
                    mma16816(cf, a0, a1, a2, a3, b0, b1);
                }
            }
            __syncthreads();
        }
        stage(0);   // prefetch P3 chunk 0
        // store partial frags to s_p [kh*8+m][16][8] f32 at O_C
        int g = lane >> 2, tc = lane & 3;
        float* sp = sm + O_C;
        *(float2*)(sp + ((kh * 8 + m) * 16 + g) * 8 + 2 * tc)     = make_float2(cf[0], cf[1]);
        *(float2*)(sp + ((kh * 8 + m) * 16 + g + 8) * 8 + 2 * tc) = make_float2(cf[2], cf[3]);
    }
    __syncthreads();
    // ebar[h][d] at O_C+2048
    for (int i = t; i < 1024; i += 512) {
        int h = i >> 7, d = i & 127, m2 = d >> 4, g2 = d & 15;
        sm[O_C + 2048 + i] = sm[O_C + (m2 * 16 + g2) * 8 + h]
                           + sm[O_C + ((8 + m2) * 16 + g2) * 8 + h];
    }
    __syncthreads();

    // ---- Phase 2b: heads -> glimpse -> gtilde (+ gt16), split accumulators ----
    if (t < 128) {
        int h = t >> 4;
        const float* eb = sm + O_C + 2048 + h * 128;
        float a0 = 0.f, a1 = 0.f;
        #pragma unroll 4
        for (int d = 0; d < DD; d += 2) {
            a0 += eb[d] * Wn[d * 384 + 128 + t];
            a1 += eb[d + 1] * Wn[(d + 1) * 384 + 128 + t];
        }
        sm[O_S0 + t] = a0 + a1;
    }
    __syncthreads();
    if (t < 128) {
        float a0 = 0.f, a1 = 0.f;
        #pragma unroll 4
        for (int i = 0; i < DD; i += 2) {
            a0 += sm[O_S0 + i] * Wo[i * DD + t];
            a1 += sm[O_S0 + i + 1] * Wo[(i + 1) * DD + t];
        }
        sm[O_S1 + t] = a0 + a1;
    }
    __syncthreads();
    if (t < 128) {
        const float* w = Wn + t * 384 + 256;
        float a0 = 0.f, a1 = 0.f;
        #pragma unroll 4
        for (int j = 0; j < DD; j += 2) {
            a0 += w[j] * sm[O_S1 + j];
            a1 += w[j + 1] * sm[O_S1 + j + 1];
        }
        sm[O_S2 + t] = (a0 + a1) * 0.08838834764831845f;
    }
    __syncthreads();
    if (t < 64) ((u32*)(sm + O_GT16))[t] = f2h2(sm[O_S2 + 2 * t], sm[O_S2 + 2 * t + 1]);

    // ---- Phase 3: logits via mma (gt in B col 0), double-buffered ----
    float* s_lg = sm + O_C;
    float lmax = -1e30f;
    {
        float cf[4];
        const int g = lane >> 2;
        for (int ch = 0; ch < 8; ch++) {
            int R = ch >> 1, C = ch & 1;
            if (ch + 1 < 8) {
                stage(ch + 1);
                asm volatile("cp.async.wait_group 1;" ::: "memory");
            } else {
                asm volatile("cp.async.wait_group 0;" ::: "memory");
            }
            __syncthreads();
            if (C == 0) { cf[0] = cf[1] = cf[2] = cf[3] = 0.f; }
            const u32 bufb = sbase + (u32)((ch & 1) * 36864);
            #pragma unroll
            for (int kl = 0; kl < 4; kl++) {
                int kb = C * 64 + kl * 16;
                u32 b0 = 0, b1 = 0;
                if (lane < 4) {
                    b0 = *(const u32*)(smh + 2 * O_GT16 + kb + 2 * lane);
                    b1 = *(const u32*)(smh + 2 * O_GT16 + kb + 2 * lane + 8);
                }
                u32 addr = bufb + (u32)((warp * 16 + (lane & 15)) * 144 + (lane >> 4) * 16 + kl * 32);
                u32 a0, a1, a2, a3;
                ldsm4(addr, a0, a1, a2, a3);
                mma16816(cf, a0, a1, a2, a3, b0, b1);
            }
            if (C == 1 && (lane & 3) == 0) {
                int r0 = R * 256 + warp * 16 + g, r1 = r0 + 8;
                if (r0 < NN) {
                    float v = tanh_fast(cf[0]) * 10.0f;
                    if (mkB[r0]) v = NEGV;
                    s_lg[r0] = v; lmax = fmaxf(lmax, v);
                }
                if (r1 < NN) {
                    float v = tanh_fast(cf[2]) * 10.0f;
                    if (mkB[r1]) v = NEGV;
                    s_lg[r1] = v; lmax = fmaxf(lmax, v);
                }
            }
            __syncthreads();
        }
    }
    // ---- log-softmax over 1000 ----
    #pragma unroll
    for (int o = 16; o > 0; o >>= 1) lmax = fmaxf(lmax, __shfl_xor_sync(~0u, lmax, o));
    if (lane == 0) sm[O_RED + warp] = lmax;
    __syncthreads();
    float bmax = sm[O_RED + 0];
    #pragma unroll
    for (int w = 1; w < 16; w++) bmax = fmaxf(bmax, sm[O_RED + w]);
    float ls = 0.f;
    for (int n = t; n < NN; n += 512) ls += __expf(s_lg[n] - bmax);
    #pragma unroll
    for (int o = 16; o > 0; o >>= 1) ls += __shfl_xor_sync(~0u, ls, o);
    if (lane == 0) sm[O_RED + 16 + warp] = ls;
    __syncthreads();
    float tot = sm[O_RED + 16];
    #pragma unroll
    for (int w = 1; w < 16; w++) tot += sm[O_RED + 16 + w];
    float logZ = bmax + logf(tot);
    float* outB = out + (size_t)b * NN;
    for (int n = t; n < NN; n += 512) outB[n] = s_lg[n] - logZ;
}

extern "C" void kernel_launch(void* const* d_in, const int* in_sizes, int n_in,
                              void* d_out, int out_size) {
    const float* emb = (const float*)d_in[0];
    const float* Wn  = (const float*)d_in[1];
    const float* Wf  = (const float*)d_in[2];
    const float* Ws  = (const float*)d_in[3];
    const float* Wo  = (const float*)d_in[4];
    const int* fidx  = (const int*)d_in[5];
    const int* lidx  = (const int*)d_in[6];
    const int* mask  = (const int*)d_in[7];
    float* out = (float*)d_out;
    cudaFuncSetAttribute(attn_v11, cudaFuncAttributeMaxDynamicSharedMemorySize, SM_WORDS * 4);
    attn_v11<<<256, 512, SM_WORDS * 4>>>(emb, Wn, Wf, Ws, Wo, fidx, lidx, mask, out);
}